// round 14
// baseline (speedup 1.0000x reference)
#include <cuda_runtime.h>
#include <cuda_bf16.h>
#include <cstdint>

typedef unsigned long long ULL;

#define SEQ   2048
#define NB    8
#define NTOK  (SEQ * NB)
#define DIMD  1024
#define SSMD  64
#define RNND  128
#define P1LD  512
#define WROWS 1536

#define AST      40                    // smem tile stride in bf16 (80 B)
#define TILE_SB  (128 * AST * 2)       // 10240 B per operand tile
#define STAGE_SB (4 * TILE_SB)         // Ah, Al, Bh, Bl
#define DSMB     (2 * STAGE_SB)        // 81920 B double buffer
#define RINGF    392
#define RINGB    (RINGF * 4)           // 1568 B per ring slot

// ---------------- device scratch ----------------
__device__ float g_P1[(size_t)NTOK * P1LD];
__device__ float g_dx[(size_t)NTOK * DIMD];
__device__ float g_b1[P1LD];
__device__ __nv_bfloat16 g_xhi[(size_t)NTOK * DIMD];
__device__ __nv_bfloat16 g_xlo[(size_t)NTOK * DIMD];
__device__ __nv_bfloat16 g_whi[(size_t)WROWS * DIMD];
__device__ __nv_bfloat16 g_wlo[(size_t)WROWS * DIMD];
__device__ __nv_bfloat16 g_hhi[(size_t)NTOK * 192];   // gated h, bf16 hi
__device__ __nv_bfloat16 g_hlo[(size_t)NTOK * 192];   // gated h, bf16 lo
__device__ __nv_bfloat16 g_wohi[DIMD * 192];          // [Cw|proj] bf16 hi
__device__ __nv_bfloat16 g_wolo[DIMD * 192];          // [Cw|proj] bf16 lo
__device__ int g_p1flag[128];                         // per m-tile: 4 = ready
__device__ int g_dxflag[128];                         // per m-tile: 8 = ready
__device__ int g_scanflagG[NB];                       // GRU time-tiles done per batch
__device__ int g_scanflagS[NB];                       // SSM time-tiles done per batch

// ---------------- PTX helpers ----------------
__device__ __forceinline__ uint32_t smem_u32(const void* p) {
    uint32_t a;
    asm("{ .reg .u64 t; cvta.to.shared.u64 t, %1; cvt.u32.u64 %0, t; }" : "=r"(a) : "l"(p));
    return a;
}
__device__ __forceinline__ void cpa16(uint32_t dst, const void* src) {
    asm volatile("cp.async.cg.shared.global [%0], [%1], 16;" :: "r"(dst), "l"(src));
}
#define CP_COMMIT() asm volatile("cp.async.commit_group;" ::: "memory")
#define CP_WAIT(n)  asm volatile("cp.async.wait_group %0;" :: "n"(n) : "memory")

__device__ __forceinline__ void ldm4(uint32_t& r0, uint32_t& r1, uint32_t& r2, uint32_t& r3, uint32_t a) {
    asm volatile("ldmatrix.sync.aligned.m8n8.x4.shared.b16 {%0,%1,%2,%3}, [%4];"
                 : "=r"(r0), "=r"(r1), "=r"(r2), "=r"(r3) : "r"(a));
}
__device__ __forceinline__ void mma16816(float* d, const uint32_t* a, const uint32_t* b) {
    asm volatile(
        "mma.sync.aligned.m16n8k16.row.col.f32.bf16.bf16.f32 "
        "{%0,%1,%2,%3}, {%4,%5,%6,%7}, {%8,%9}, {%0,%1,%2,%3};"
        : "+f"(d[0]), "+f"(d[1]), "+f"(d[2]), "+f"(d[3])
        : "r"(a[0]), "r"(a[1]), "r"(a[2]), "r"(a[3]), "r"(b[0]), "r"(b[1]));
}
__device__ __forceinline__ int ld_acq(const int* p) {
    int v; asm volatile("ld.acquire.gpu.global.b32 %0, [%1];" : "=r"(v) : "l"(p) : "memory"); return v;
}

// ---------------- misc helpers ----------------
__device__ __forceinline__ float2 upk2(ULL v) {
    float2 f; asm("mov.b64 {%0,%1}, %2;" : "=f"(f.x), "=f"(f.y) : "l"(v)); return f;
}
__device__ __forceinline__ void fma2(ULL& d, ULL a, ULL b) {
    asm("fma.rn.f32x2 %0, %1, %2, %0;" : "+l"(d) : "l"(a), "l"(b));
}
__device__ __forceinline__ float sigm(float x) { return __fdividef(1.f, 1.f + __expf(-x)); }
__device__ __forceinline__ float tanhf_(float x) { return __fdividef(2.f, 1.f + __expf(-2.f * x)) - 1.f; }
__device__ __forceinline__ void splitb(float v, __nv_bfloat16& h, __nv_bfloat16& l) {
    h = __float2bfloat16(v);
    l = __float2bfloat16(v - __bfloat162float(h));
}

// ---------------- conv_w: pack & split weights (+ zero flags each replay) ----------------
__global__ void conv_w_kernel(const float* __restrict__ Bw, const float* __restrict__ Bb,
                              const float* __restrict__ W_ih, const float* __restrict__ b_ih,
                              const float* __restrict__ gate_w, const float* __restrict__ gate_b,
                              const float* __restrict__ Cw, const float* __restrict__ proj_w,
                              const float* __restrict__ Dw) {
    int i = blockIdx.x * blockDim.x + threadIdx.x;
    if (i < 128) { g_p1flag[i] = 0; g_dxflag[i] = 0; }
    if (i < NB)  { g_scanflagG[i] = 0; g_scanflagS[i] = 0; }
    if (i < WROWS * DIMD) {
        int r = i >> 10, c = i & 1023;
        float v;
        if (r < 64)        v = Bw[r * DIMD + c];
        else if (r < 448)  v = W_ih[(r - 64) * DIMD + c];
        else if (r < 450)  v = gate_w[(r - 448) * DIMD + c];
        else if (r < 512)  v = 0.f;
        else               v = Dw[(r - 512) * DIMD + c];
        __nv_bfloat16 h, l; splitb(v, h, l);
        g_whi[i] = h; g_wlo[i] = l;
    }
    if (i < DIMD * 192) {
        int d = i / 192, q = i % 192;
        float v = (q < 64) ? Cw[d * 64 + q] : proj_w[d * 128 + (q - 64)];
        __nv_bfloat16 h, l; splitb(v, h, l);
        g_wohi[i] = h; g_wolo[i] = l;
    }
    if (i < P1LD) {
        float b = 0.f;
        if (i < 64)       b = Bb[i];
        else if (i < 448) b = b_ih[i - 64];
        else if (i < 450) b = gate_b[i - 448];
        g_b1[i] = b;
    }
}

// ---------------- conv_x: split x into bf16 hi/lo ----------------
__global__ __launch_bounds__(256) void conv_x_kernel(const float* __restrict__ x) {
    int i = blockIdx.x * blockDim.x + threadIdx.x;
    float4 v = *(const float4*)(x + (size_t)i * 4);
    __nv_bfloat16 h0, l0, h1, l1, h2, l2, h3, l3;
    splitb(v.x, h0, l0); splitb(v.y, h1, l1); splitb(v.z, h2, l2); splitb(v.w, h3, l3);
    __nv_bfloat162* dh = (__nv_bfloat162*)(g_xhi + (size_t)i * 4);
    __nv_bfloat162* dl = (__nv_bfloat162*)(g_xlo + (size_t)i * 4);
    dh[0] = __nv_bfloat162(h0, h1); dh[1] = __nv_bfloat162(h2, h3);
    dl[0] = __nv_bfloat162(l0, l1); dl[1] = __nv_bfloat162(l2, l3);
}

// ---------------- HMMA 128x128 tile core, 256 threads (8 warps), templated K ----------------
template <int KCHUNKS>
__device__ void hmma_acc(const __nv_bfloat16* __restrict__ Ah, const __nv_bfloat16* __restrict__ Al,
                         const __nv_bfloat16* __restrict__ Bh, const __nv_bfloat16* __restrict__ Bl,
                         int lda, char* smem, float (*acc)[4][4])   // acc[4][4][4]
{
    const int tid = threadIdx.x, lane = tid & 31, warp = tid >> 5;
    const int wm = warp >> 2, wn = warp & 3;
    const uint32_t sbase = smem_u32(smem);
    const __nv_bfloat16* srcs[4] = {Ah, Al, Bh, Bl};

#pragma unroll
    for (int t = 0; t < 8; t++) {
        int job = tid + t * 256;
        int tile = job >> 9, rem = job & 511;
        int row = rem >> 2, c4 = rem & 3;
        cpa16(sbase + tile * TILE_SB + row * (AST * 2) + c4 * 16,
              srcs[tile] + (size_t)row * lda + c4 * 8);
    }
    CP_COMMIT();

    const int a_r  = (lane < 16) ? lane : lane - 16;
    const int a_c8 = (lane < 16) ? 0 : 8;
    const int b_r  = (lane & 7) + ((lane >= 16) ? 8 : 0);
    const int b_c8 = ((lane & 15) >= 8) ? 8 : 0;

    for (int ch = 0; ch < KCHUNKS; ch++) {
        int s = ch & 1;
        if (ch + 1 < KCHUNKS) {
            int s2 = s ^ 1;
#pragma unroll
            for (int t = 0; t < 8; t++) {
                int job = tid + t * 256;
                int tile = job >> 9, rem = job & 511;
                int row = rem >> 2, c4 = rem & 3;
                cpa16(sbase + s2 * STAGE_SB + tile * TILE_SB + row * (AST * 2) + c4 * 16,
                      srcs[tile] + (size_t)row * lda + (ch + 1) * 32 + c4 * 8);
            }
            CP_COMMIT();
            CP_WAIT(1);
        } else {
            CP_WAIT(0);
        }
        __syncthreads();

        uint32_t stb = sbase + s * STAGE_SB;
#pragma unroll
        for (int kk = 0; kk < 2; kk++) {
            uint32_t ah[4][4], al[4][4], bh[4][2], bl[4][2];
#pragma unroll
            for (int mt = 0; mt < 4; mt++) {
                uint32_t ra = stb + (wm * 64 + mt * 16 + a_r) * (AST * 2) + (kk * 16 + a_c8) * 2;
                ldm4(ah[mt][0], ah[mt][1], ah[mt][2], ah[mt][3], ra);
                ldm4(al[mt][0], al[mt][1], al[mt][2], al[mt][3], ra + TILE_SB);
            }
#pragma unroll
            for (int np = 0; np < 2; np++) {
                uint32_t rb = stb + 2 * TILE_SB + (wn * 32 + np * 16 + b_r) * (AST * 2) + (kk * 16 + b_c8) * 2;
                uint32_t r0, r1, r2, r3;
                ldm4(r0, r1, r2, r3, rb);
                bh[np*2][0] = r0; bh[np*2][1] = r1; bh[np*2+1][0] = r2; bh[np*2+1][1] = r3;
                ldm4(r0, r1, r2, r3, rb + TILE_SB);
                bl[np*2][0] = r0; bl[np*2][1] = r1; bl[np*2+1][0] = r2; bl[np*2+1][1] = r3;
            }
#pragma unroll
            for (int mt = 0; mt < 4; mt++)
#pragma unroll
                for (int nt = 0; nt < 4; nt++) {
                    mma16816(acc[mt][nt], ah[mt], bh[nt]);
                    mma16816(acc[mt][nt], ah[mt], bl[nt]);
                    mma16816(acc[mt][nt], al[mt], bh[nt]);
                }
        }
        __syncthreads();
    }
}

__device__ void hmma_store_bias(float (*acc)[4][4], float* __restrict__ Cout, int ldc,
                                const float* __restrict__ bias) {
    const int tid = threadIdx.x, lane = tid & 31, warp = tid >> 5;
    const int wm = warp >> 2, wn = warp & 3;
    const int g = lane >> 2, tg = lane & 3;
#pragma unroll
    for (int mt = 0; mt < 4; mt++) {
#pragma unroll
        for (int nt = 0; nt < 4; nt++) {
            int row = wm * 64 + mt * 16 + g;
            int col = wn * 32 + nt * 8 + tg * 2;
            float bx0 = 0.f, bx1 = 0.f;
            if (bias) { bx0 = bias[col]; bx1 = bias[col + 1]; }
            *(float2*)(Cout + (size_t)row * ldc + col) =
                make_float2(acc[mt][nt][0] + bx0, acc[mt][nt][1] + bx1);
            *(float2*)(Cout + (size_t)(row + 8) * ldc + col) =
                make_float2(acc[mt][nt][2] + bx0, acc[mt][nt][3] + bx1);
        }
    }
}

// ---------------- waits ----------------
__device__ __forceinline__ void wait_p1_tile(int mt) {
    while (ld_acq(&g_p1flag[mt]) < 4) { }
    __threadfence();
}

// ---------------- mega: 0-15 scan | 16-527 p1 | 528-1551 dx | 1552-2575 out ----------------
__global__ __launch_bounds__(256, 1) void mega_kernel(
    const float* __restrict__ A, const float* __restrict__ W_hh, const float* __restrict__ b_hh,
    const float* __restrict__ Cb, const float* __restrict__ Db,
    const float* __restrict__ pb, float* __restrict__ out) {
    extern __shared__ char dsm[];
    __shared__ __align__(16) float sh[2][136];
    __shared__ __align__(16) float ring[8][RINGF];
    const int tid = threadIdx.x;

    if (blockIdx.x >= 1552) {
        // ---- out tile (tt-major): waits on scan progress + dx tile ----
        const int ot = blockIdx.x - 1552;
        const int tt = ot >> 6, rem = ot & 63;
        const int b = rem >> 3, nt = rem & 7;
        const int mt = b * 16 + tt;
        if (tid == 0) {
            while (ld_acq(&g_scanflagG[b]) < tt + 1) __nanosleep(256);
            while (ld_acq(&g_scanflagS[b]) < tt + 1) __nanosleep(256);
            while (ld_acq(&g_dxflag[mt]) < 8) __nanosleep(256);
        }
        __syncthreads();

        float acc[4][4][4];
#pragma unroll
        for (int a = 0; a < 4; a++)
#pragma unroll
            for (int bq = 0; bq < 4; bq++)
#pragma unroll
                for (int c = 0; c < 4; c++) acc[a][bq][c] = 0.f;
        hmma_acc<6>(g_hhi + (size_t)mt * 128 * 192, g_hlo + (size_t)mt * 128 * 192,
                    g_wohi + (size_t)nt * 128 * 192, g_wolo + (size_t)nt * 128 * 192,
                    192, dsm, acc);

        const int lane = tid & 31, warp = tid >> 5;
        const int wm = warp >> 2, wn = warp & 3;
        const int g = lane >> 2, tg = lane & 3;
#pragma unroll
        for (int mt4 = 0; mt4 < 4; mt4++) {
            int r0 = wm * 64 + mt4 * 16 + g;
#pragma unroll
            for (int half = 0; half < 2; half++) {
                int row = r0 + half * 8;
                int t = mt * 128 + row;
                float g0 = sigm(g_P1[(size_t)t * P1LD + 448]);
                float g1 = sigm(g_P1[(size_t)t * P1LD + 449]);
                const float* dxrow = g_dx + (size_t)t * DIMD;
                float* orow = out + (size_t)t * DIMD;
#pragma unroll
                for (int nt4 = 0; nt4 < 4; nt4++) {
                    int col = nt * 128 + wn * 32 + nt4 * 8 + tg * 2;
                    float2 dxv = *(const float2*)(dxrow + col);
                    float a0 = acc[mt4][nt4][half * 2 + 0];
                    float a1 = acc[mt4][nt4][half * 2 + 1];
                    float2 o;
                    o.x = a0 + g0 * (Cb[col]     + Db[col]     + dxv.x) + g1 * pb[col];
                    o.y = a1 + g0 * (Cb[col + 1] + Db[col + 1] + dxv.y) + g1 * pb[col + 1];
                    *(float2*)(orow + col) = o;
                }
            }
        }
        return;
    }

    if (blockIdx.x >= 528) {
        // ---- dx tile (tt-major) ----
        const int bt = blockIdx.x - 528;
        const int tt = bt >> 6, rem = bt & 63;
        const int b = rem >> 3, nt = rem & 7;
        const int mt = b * 16 + tt;
        float acc[4][4][4];
#pragma unroll
        for (int a = 0; a < 4; a++)
#pragma unroll
            for (int bq = 0; bq < 4; bq++)
#pragma unroll
                for (int c = 0; c < 4; c++) acc[a][bq][c] = 0.f;
        hmma_acc<32>(g_xhi + (size_t)mt * 128 * DIMD, g_xlo + (size_t)mt * 128 * DIMD,
                     g_whi + (size_t)(512 + nt * 128) * DIMD, g_wlo + (size_t)(512 + nt * 128) * DIMD,
                     DIMD, dsm, acc);
        hmma_store_bias(acc, g_dx + (size_t)mt * 128 * DIMD + nt * 128, DIMD, nullptr);
        __threadfence();
        __syncthreads();
        if (tid == 0) atomicAdd(&g_dxflag[mt], 1);
        return;
    }

    if (blockIdx.x >= 16) {
        // ---- p1 tile (tt-major) ----
        const int idx = blockIdx.x - 16;
        const int tt = idx >> 5, rem = idx & 31;
        const int b = rem >> 2, nt = rem & 3;
        const int mt = b * 16 + tt;
        float acc[4][4][4];
#pragma unroll
        for (int a = 0; a < 4; a++)
#pragma unroll
            for (int bq = 0; bq < 4; bq++)
#pragma unroll
                for (int c = 0; c < 4; c++) acc[a][bq][c] = 0.f;
        hmma_acc<32>(g_xhi + (size_t)mt * 128 * DIMD, g_xlo + (size_t)mt * 128 * DIMD,
                     g_whi + (size_t)nt * 128 * DIMD, g_wlo + (size_t)nt * 128 * DIMD,
                     DIMD, dsm, acc);
        hmma_store_bias(acc, g_P1 + (size_t)mt * 128 * P1LD + nt * 128, P1LD, g_b1 + nt * 128);
        __threadfence();
        __syncthreads();
        if (tid == 0) atomicAdd(&g_p1flag[mt], 1);
        return;
    }

    if (blockIdx.x < 8) {
        // ---- GRU ----
        const int b = blockIdx.x;
        const int j = tid >> 1, k = tid & 1;
        const int jpos = j + ((j >= 64) ? 4 : 0);
        const float* p1 = g_P1 + (size_t)b * SEQ * P1LD;

        ULL wr[32], wz[32], wn[32];
        const float* wb = W_hh + (size_t)j * RNND + k * 64;
#pragma unroll
        for (int i = 0; i < 32; i++) {
            wr[i] = *(const ULL*)(wb + 2 * i);
            wz[i] = *(const ULL*)(wb + 128 * RNND + 2 * i);
            wn[i] = *(const ULL*)(wb + 256 * RNND + 2 * i);
        }
        const float br = b_hh[j], bz = b_hh[RNND + j], bn = b_hh[2 * RNND + j];
        if (tid < 136) { sh[0][tid] = 0.f; sh[1][tid] = 0.f; }

        wait_p1_tile(b * 16);
        const uint32_t rbase = smem_u32(&ring[0][0]);
#pragma unroll
        for (int pre = 0; pre < 7; pre++) {
            if (tid < 96)       cpa16(rbase + pre * RINGB + tid * 16, p1 + (size_t)pre * P1LD + 64 + tid * 4);
            else if (tid == 96) cpa16(rbase + pre * RINGB + 1536,     p1 + (size_t)pre * P1LD + 448);
            CP_COMMIT();
        }
        CP_WAIT(6);
        __syncthreads();

        __nv_bfloat16* hi_out = g_hhi + (size_t)b * SEQ * 192 + 64;
        __nv_bfloat16* lo_out = g_hlo + (size_t)b * SEQ * 192 + 64;
        int buf = 0;

        for (int t = 0; t < SEQ; t++) {
            int tp = t + 7;
            if (tp < SEQ) {
                if ((tp & 127) == 0) wait_p1_tile(b * 16 + (tp >> 7));
                if (tid < 96)       cpa16(rbase + (tp & 7) * RINGB + tid * 16, p1 + (size_t)tp * P1LD + 64 + tid * 4);
                else if (tid == 96) cpa16(rbase + (tp & 7) * RINGB + 1536,     p1 + (size_t)tp * P1LD + 448);
            }
            CP_COMMIT();

            const float* rg = ring[t & 7];
            float ir = rg[j], iz = rg[128 + j], in0 = rg[256 + j];

            ULL ar = 0ull, az = 0ull, an = 0ull;
            const ulonglong2* h4 = (const ulonglong2*)&sh[buf][k * 68];
#pragma unroll
            for (int i = 0; i < 16; i++) {
                ulonglong2 hv = h4[i];
                fma2(ar, wr[2*i], hv.x); fma2(az, wz[2*i], hv.x); fma2(an, wn[2*i], hv.x);
                fma2(ar, wr[2*i+1], hv.y); fma2(az, wz[2*i+1], hv.y); fma2(an, wn[2*i+1], hv.y);
            }
            float2 fr = upk2(ar), fz = upk2(az), fn = upk2(an);
            float sr = fr.x + fr.y, sz = fz.x + fz.y, sn = fn.x + fn.y;
            sr += __shfl_xor_sync(0xffffffffu, sr, 1);
            sz += __shfl_xor_sync(0xffffffffu, sz, 1);
            sn += __shfl_xor_sync(0xffffffffu, sn, 1);
            float hold = sh[buf][jpos];
            float r = sigm(ir + br + sr);
            float z = sigm(iz + bz + sz);
            float n = tanhf_(in0 + r * (sn + bn));
            float hnew = n + z * (hold - n);
            sh[buf ^ 1][jpos] = hnew;
            if (k == 0) {
                float g1t = sigm(rg[385]);
                __nv_bfloat16 hh, hl; splitb(hnew * g1t, hh, hl);
                hi_out[(size_t)t * 192 + j] = hh;
                lo_out[(size_t)t * 192 + j] = hl;
            }
            buf ^= 1;
            CP_WAIT(6);
            __syncthreads();
            if ((t & 127) == 127) {
                __threadfence();
                __syncthreads();
                if (tid == 0) atomicAdd(&g_scanflagG[b], 1);
            }
        }
    } else {
        // ---- SSM ----
        const int b = blockIdx.x - 8;
        const int j = tid >> 2, k = tid & 3;
        float* shf = (float*)sh;
        const int jpos = (j >> 4) * 20 + (j & 15);
        const float* p1 = g_P1 + (size_t)b * SEQ * P1LD;
        ULL wa[8];
        const float* ab = A + (size_t)j * SSMD + k * 16;
#pragma unroll
        for (int i = 0; i < 8; i++) wa[i] = *(const ULL*)(ab + 2 * i);
        if (tid < 160) shf[tid] = 0.f;

        wait_p1_tile(b * 16);
        const uint32_t rbase = smem_u32(&ring[0][0]);
#pragma unroll
        for (int pre = 0; pre < 7; pre++) {
            if (tid < 16)       cpa16(rbase + pre * RINGB + tid * 16, p1 + (size_t)pre * P1LD + tid * 4);
            else if (tid == 16) cpa16(rbase + pre * RINGB + 1536,     p1 + (size_t)pre * P1LD + 448);
            CP_COMMIT();
        }
        CP_WAIT(6);
        __syncthreads();

        __nv_bfloat16* hi_out = g_hhi + (size_t)b * SEQ * 192;
        __nv_bfloat16* lo_out = g_hlo + (size_t)b * SEQ * 192;
        int buf = 0;

        for (int t = 0; t < SEQ; t++) {
            int tp = t + 7;
            if (tp < SEQ) {
                if ((tp & 127) == 0) wait_p1_tile(b * 16 + (tp >> 7));
                if (tid < 16)       cpa16(rbase + (tp & 7) * RINGB + tid * 16, p1 + (size_t)tp * P1LD + tid * 4);
                else if (tid == 16) cpa16(rbase + (tp & 7) * RINGB + 1536,     p1 + (size_t)tp * P1LD + 448);
            }
            CP_COMMIT();

            const float* rg = ring[t & 7];
            float bx = rg[j];
            ULL acc = 0ull;
            const ULL* hh4 = (const ULL*)(shf + buf * 80 + k * 20);
#pragma unroll
            for (int i = 0; i < 8; i++) fma2(acc, wa[i], hh4[i]);
            float2 fa = upk2(acc);
            float s = fa.x + fa.y;
            s += __shfl_xor_sync(0xffffffffu, s, 1);
            s += __shfl_xor_sync(0xffffffffu, s, 2);
            float pre = s + bx;
            float hnew = pre * sigm(pre);
            shf[(buf ^ 1) * 80 + jpos] = hnew;
            if (k == 0) {
                float g0t = sigm(rg[384]);
                __nv_bfloat16 hh, hl; splitb(hnew * g0t, hh, hl);
                hi_out[(size_t)t * 192 + j] = hh;
                lo_out[(size_t)t * 192 + j] = hl;
            }
            buf ^= 1;
            CP_WAIT(6);
            __syncthreads();
            if ((t & 127) == 127) {
                __threadfence();
                __syncthreads();
                if (tid == 0) atomicAdd(&g_scanflagS[b], 1);
            }
        }
    }
}

extern "C" void kernel_launch(void* const* d_in, const int* in_sizes, int n_in,
                              void* d_out, int out_size) {
    const float* x      = (const float*)d_in[0];
    const float* A      = (const float*)d_in[1];
    const float* Bw     = (const float*)d_in[2];
    const float* Bb     = (const float*)d_in[3];
    const float* Cw     = (const float*)d_in[4];
    const float* Cb     = (const float*)d_in[5];
    const float* Dw     = (const float*)d_in[6];
    const float* Db     = (const float*)d_in[7];
    const float* W_ih   = (const float*)d_in[8];
    const float* b_ih   = (const float*)d_in[9];
    const float* W_hh   = (const float*)d_in[10];
    const float* b_hh   = (const float*)d_in[11];
    const float* proj_w = (const float*)d_in[12];
    const float* proj_b = (const float*)d_in[13];
    const float* gate_w = (const float*)d_in[14];
    const float* gate_b = (const float*)d_in[15];
    float* out = (float*)d_out;

    cudaFuncSetAttribute(mega_kernel, cudaFuncAttributeMaxDynamicSharedMemorySize, DSMB);

    conv_w_kernel<<<(WROWS * DIMD + 255) / 256, 256>>>(Bw, Bb, W_ih, b_ih, gate_w, gate_b, Cw, proj_w, Dw);
    conv_x_kernel<<<(NTOK * DIMD / 4) / 256, 256>>>(x);
    mega_kernel<<<16 + 512 + 1024 + 1024, 256, DSMB>>>(A, W_hh, b_hh, Cb, Db, proj_b, out);
}

// round 16
// speedup vs baseline: 1.1311x; 1.1311x over previous
#include <cuda_runtime.h>
#include <cuda_bf16.h>
#include <cstdint>

typedef unsigned long long ULL;

#define SEQ   2048
#define NB    8
#define NTOK  (SEQ * NB)
#define DIMD  1024
#define SSMD  64
#define RNND  128
#define P1LD  512
#define WROWS 1536

#define AST      40                    // smem tile stride in bf16 (80 B)
#define TILE_SB  (128 * AST * 2)       // 10240 B per operand tile
#define STAGE_SB (4 * TILE_SB)         // Ah, Al, Bh, Bl
#define DSMB     (2 * STAGE_SB)        // 81920 B double buffer

#define CONVX_BLKS 16384               // NTOK*DIMD/4/256
#define CONVW_BLKS 6144                // WROWS*DIMD/256

// mega grid layout
#define BID_P1   16
#define BID_DX   (BID_P1 + 512)        // 528
#define BID_TAIL (BID_DX + 1024)       // 1552: per tt: 8 split + 64 out = 72
#define N_MEGA   (BID_TAIL + 16 * 72)  // 2704

// ---------------- device scratch ----------------
__device__ float g_P1[(size_t)NTOK * P1LD];
__device__ float g_dx[(size_t)NTOK * DIMD];
__device__ float g_HsHr[(size_t)NTOK * 192];
__device__ float g_b1[P1LD];
__device__ __nv_bfloat16 g_xhi[(size_t)NTOK * DIMD];
__device__ __nv_bfloat16 g_xlo[(size_t)NTOK * DIMD];
__device__ __nv_bfloat16 g_whi[(size_t)WROWS * DIMD];
__device__ __nv_bfloat16 g_wlo[(size_t)WROWS * DIMD];
__device__ __nv_bfloat16 g_hhi[(size_t)NTOK * 192];   // gated h, bf16 hi
__device__ __nv_bfloat16 g_hlo[(size_t)NTOK * 192];   // gated h, bf16 lo
__device__ __nv_bfloat16 g_wohi[DIMD * 192];          // [Cw|proj] bf16 hi
__device__ __nv_bfloat16 g_wolo[DIMD * 192];          // [Cw|proj] bf16 lo
__device__ int g_p1flag[128];                         // per m-tile: 4 = ready
__device__ int g_dxflag[128];                         // per m-tile: 8 = ready
__device__ int g_sflag[128];                          // per m-tile: 1 = split done
__device__ int g_scanflagG[NB];                       // GRU time-tiles done
__device__ int g_scanflagS[NB];                       // SSM time-tiles done

// ---------------- PTX helpers ----------------
__device__ __forceinline__ uint32_t smem_u32(const void* p) {
    uint32_t a;
    asm("{ .reg .u64 t; cvta.to.shared.u64 t, %1; cvt.u32.u64 %0, t; }" : "=r"(a) : "l"(p));
    return a;
}
__device__ __forceinline__ void cpa16(uint32_t dst, const void* src) {
    asm volatile("cp.async.cg.shared.global [%0], [%1], 16;" :: "r"(dst), "l"(src));
}
#define CP_COMMIT() asm volatile("cp.async.commit_group;" ::: "memory")
#define CP_WAIT(n)  asm volatile("cp.async.wait_group %0;" :: "n"(n) : "memory")

__device__ __forceinline__ void ldm4(uint32_t& r0, uint32_t& r1, uint32_t& r2, uint32_t& r3, uint32_t a) {
    asm volatile("ldmatrix.sync.aligned.m8n8.x4.shared.b16 {%0,%1,%2,%3}, [%4];"
                 : "=r"(r0), "=r"(r1), "=r"(r2), "=r"(r3) : "r"(a));
}
__device__ __forceinline__ void mma16816(float* d, const uint32_t* a, const uint32_t* b) {
    asm volatile(
        "mma.sync.aligned.m16n8k16.row.col.f32.bf16.bf16.f32 "
        "{%0,%1,%2,%3}, {%4,%5,%6,%7}, {%8,%9}, {%0,%1,%2,%3};"
        : "+f"(d[0]), "+f"(d[1]), "+f"(d[2]), "+f"(d[3])
        : "r"(a[0]), "r"(a[1]), "r"(a[2]), "r"(a[3]), "r"(b[0]), "r"(b[1]));
}
__device__ __forceinline__ int ld_acq(const int* p) {
    int v; asm volatile("ld.acquire.gpu.global.b32 %0, [%1];" : "=r"(v) : "l"(p) : "memory"); return v;
}

// ---------------- misc helpers ----------------
__device__ __forceinline__ float2 upk2(ULL v) {
    float2 f; asm("mov.b64 {%0,%1}, %2;" : "=f"(f.x), "=f"(f.y) : "l"(v)); return f;
}
__device__ __forceinline__ void fma2(ULL& d, ULL a, ULL b) {
    asm("fma.rn.f32x2 %0, %1, %2, %0;" : "+l"(d) : "l"(a), "l"(b));
}
__device__ __forceinline__ float sigm(float x) { return __fdividef(1.f, 1.f + __expf(-x)); }
__device__ __forceinline__ float tanhf_(float x) { return __fdividef(2.f, 1.f + __expf(-2.f * x)) - 1.f; }
__device__ __forceinline__ void splitb(float v, __nv_bfloat16& h, __nv_bfloat16& l) {
    h = __float2bfloat16(v);
    l = __float2bfloat16(v - __bfloat162float(h));
}

// ---------------- conv: blocks 0..CONVX-1 split x; rest pack/split weights ----------------
__global__ __launch_bounds__(256) void conv_kernel(
    const float* __restrict__ x,
    const float* __restrict__ Bw, const float* __restrict__ Bb,
    const float* __restrict__ W_ih, const float* __restrict__ b_ih,
    const float* __restrict__ gate_w, const float* __restrict__ gate_b,
    const float* __restrict__ Cw, const float* __restrict__ proj_w,
    const float* __restrict__ Dw) {
    if (blockIdx.x < CONVX_BLKS) {
        int i = blockIdx.x * blockDim.x + threadIdx.x;
        float4 v = *(const float4*)(x + (size_t)i * 4);
        __nv_bfloat16 h0, l0, h1, l1, h2, l2, h3, l3;
        splitb(v.x, h0, l0); splitb(v.y, h1, l1); splitb(v.z, h2, l2); splitb(v.w, h3, l3);
        __nv_bfloat162* dh = (__nv_bfloat162*)(g_xhi + (size_t)i * 4);
        __nv_bfloat162* dl = (__nv_bfloat162*)(g_xlo + (size_t)i * 4);
        dh[0] = __nv_bfloat162(h0, h1); dh[1] = __nv_bfloat162(h2, h3);
        dl[0] = __nv_bfloat162(l0, l1); dl[1] = __nv_bfloat162(l2, l3);
        return;
    }
    int i = (blockIdx.x - CONVX_BLKS) * blockDim.x + threadIdx.x;
    if (i < 128) { g_p1flag[i] = 0; g_dxflag[i] = 0; g_sflag[i] = 0; }
    if (i < NB)  { g_scanflagG[i] = 0; g_scanflagS[i] = 0; }
    if (i < WROWS * DIMD) {
        int r = i >> 10, c = i & 1023;
        float v;
        if (r < 64)        v = Bw[r * DIMD + c];
        else if (r < 448)  v = W_ih[(r - 64) * DIMD + c];
        else if (r < 450)  v = gate_w[(r - 448) * DIMD + c];
        else if (r < 512)  v = 0.f;
        else               v = Dw[(r - 512) * DIMD + c];
        __nv_bfloat16 h, l; splitb(v, h, l);
        g_whi[i] = h; g_wlo[i] = l;
    }
    if (i < DIMD * 192) {
        int d = i / 192, q = i % 192;
        float v = (q < 64) ? Cw[d * 64 + q] : proj_w[d * 128 + (q - 64)];
        __nv_bfloat16 h, l; splitb(v, h, l);
        g_wohi[i] = h; g_wolo[i] = l;
    }
    if (i < P1LD) {
        float b = 0.f;
        if (i < 64)       b = Bb[i];
        else if (i < 448) b = b_ih[i - 64];
        else if (i < 450) b = gate_b[i - 448];
        g_b1[i] = b;
    }
}

// ---------------- HMMA 128x128 tile core, 256 threads (8 warps), templated K ----------------
template <int KCHUNKS>
__device__ void hmma_acc(const __nv_bfloat16* __restrict__ Ah, const __nv_bfloat16* __restrict__ Al,
                         const __nv_bfloat16* __restrict__ Bh, const __nv_bfloat16* __restrict__ Bl,
                         int lda, char* smem, float (*acc)[4][4])   // acc[4][4][4]
{
    const int tid = threadIdx.x, lane = tid & 31, warp = tid >> 5;
    const int wm = warp >> 2, wn = warp & 3;
    const uint32_t sbase = smem_u32(smem);
    const __nv_bfloat16* srcs[4] = {Ah, Al, Bh, Bl};

#pragma unroll
    for (int t = 0; t < 8; t++) {
        int job = tid + t * 256;
        int tile = job >> 9, rem = job & 511;
        int row = rem >> 2, c4 = rem & 3;
        cpa16(sbase + tile * TILE_SB + row * (AST * 2) + c4 * 16,
              srcs[tile] + (size_t)row * lda + c4 * 8);
    }
    CP_COMMIT();

    const int a_r  = (lane < 16) ? lane : lane - 16;
    const int a_c8 = (lane < 16) ? 0 : 8;
    const int b_r  = (lane & 7) + ((lane >= 16) ? 8 : 0);
    const int b_c8 = ((lane & 15) >= 8) ? 8 : 0;

    for (int ch = 0; ch < KCHUNKS; ch++) {
        int s = ch & 1;
        if (ch + 1 < KCHUNKS) {
            int s2 = s ^ 1;
#pragma unroll
            for (int t = 0; t < 8; t++) {
                int job = tid + t * 256;
                int tile = job >> 9, rem = job & 511;
                int row = rem >> 2, c4 = rem & 3;
                cpa16(sbase + s2 * STAGE_SB + tile * TILE_SB + row * (AST * 2) + c4 * 16,
                      srcs[tile] + (size_t)row * lda + (ch + 1) * 32 + c4 * 8);
            }
            CP_COMMIT();
            CP_WAIT(1);
        } else {
            CP_WAIT(0);
        }
        __syncthreads();

        uint32_t stb = sbase + s * STAGE_SB;
#pragma unroll
        for (int kk = 0; kk < 2; kk++) {
            uint32_t ah[4][4], al[4][4], bh[4][2], bl[4][2];
#pragma unroll
            for (int mt = 0; mt < 4; mt++) {
                uint32_t ra = stb + (wm * 64 + mt * 16 + a_r) * (AST * 2) + (kk * 16 + a_c8) * 2;
                ldm4(ah[mt][0], ah[mt][1], ah[mt][2], ah[mt][3], ra);
                ldm4(al[mt][0], al[mt][1], al[mt][2], al[mt][3], ra + TILE_SB);
            }
#pragma unroll
            for (int np = 0; np < 2; np++) {
                uint32_t rb = stb + 2 * TILE_SB + (wn * 32 + np * 16 + b_r) * (AST * 2) + (kk * 16 + b_c8) * 2;
                uint32_t r0, r1, r2, r3;
                ldm4(r0, r1, r2, r3, rb);
                bh[np*2][0] = r0; bh[np*2][1] = r1; bh[np*2+1][0] = r2; bh[np*2+1][1] = r3;
                ldm4(r0, r1, r2, r3, rb + TILE_SB);
                bl[np*2][0] = r0; bl[np*2][1] = r1; bl[np*2+1][0] = r2; bl[np*2+1][1] = r3;
            }
#pragma unroll
            for (int mt = 0; mt < 4; mt++)
#pragma unroll
                for (int nt = 0; nt < 4; nt++) {
                    mma16816(acc[mt][nt], ah[mt], bh[nt]);
                    mma16816(acc[mt][nt], ah[mt], bl[nt]);
                    mma16816(acc[mt][nt], al[mt], bh[nt]);
                }
        }
        __syncthreads();
    }
}

__device__ void hmma_store_bias(float (*acc)[4][4], float* __restrict__ Cout, int ldc,
                                const float* __restrict__ bias) {
    const int tid = threadIdx.x, lane = tid & 31, warp = tid >> 5;
    const int wm = warp >> 2, wn = warp & 3;
    const int g = lane >> 2, tg = lane & 3;
#pragma unroll
    for (int mt = 0; mt < 4; mt++) {
#pragma unroll
        for (int nt = 0; nt < 4; nt++) {
            int row = wm * 64 + mt * 16 + g;
            int col = wn * 32 + nt * 8 + tg * 2;
            float bx0 = 0.f, bx1 = 0.f;
            if (bias) { bx0 = bias[col]; bx1 = bias[col + 1]; }
            *(float2*)(Cout + (size_t)row * ldc + col) =
                make_float2(acc[mt][nt][0] + bx0, acc[mt][nt][1] + bx1);
            *(float2*)(Cout + (size_t)(row + 8) * ldc + col) =
                make_float2(acc[mt][nt][2] + bx0, acc[mt][nt][3] + bx1);
        }
    }
}

// ---------------- waits ----------------
__device__ __forceinline__ void wait_p1_tile(int mt) {
    while (ld_acq(&g_p1flag[mt]) < 4) { }
    __threadfence();
}

// ---------------- mega: scan | p1 | dx | (split+out per tt) ----------------
__global__ __launch_bounds__(256, 1) void mega_kernel(
    const float* __restrict__ A, const float* __restrict__ W_hh, const float* __restrict__ b_hh,
    const float* __restrict__ Cb, const float* __restrict__ Db,
    const float* __restrict__ pb, float* __restrict__ out) {
    extern __shared__ char dsm[];
    __shared__ __align__(16) float sh[2][136];
    __shared__ __align__(16) float ring[8][384];
    const int tid = threadIdx.x;

    if (blockIdx.x >= BID_TAIL) {
        const int idx = blockIdx.x - BID_TAIL;
        const int tt = idx / 72, r = idx % 72;
        if (r < 8) {
            // ---- split tile: gate + bf16 split of scan states for mt ----
            const int b = r, mt = b * 16 + tt;
            if (tid == 0) {
                while (ld_acq(&g_scanflagG[b]) < tt + 1) __nanosleep(512);
                while (ld_acq(&g_scanflagS[b]) < tt + 1) __nanosleep(512);
            }
            __syncthreads();
            const int row = tid >> 1, half = tid & 1;
            const int t = mt * 128 + row;
            float g0 = sigm(g_P1[(size_t)t * P1LD + 448]);
            float g1 = sigm(g_P1[(size_t)t * P1LD + 449]);
            const float* hrow = g_HsHr + (size_t)t * 192;
            __nv_bfloat16* hi = g_hhi + (size_t)t * 192;
            __nv_bfloat16* lo = g_hlo + (size_t)t * 192;
#pragma unroll
            for (int c = 0; c < 96; c += 2) {
                int q = half * 96 + c;
                float ga = (q < 64) ? g0 : g1;
                float gb = (q + 1 < 64) ? g0 : g1;
                float2 hv = *(const float2*)(hrow + q);
                __nv_bfloat16 h0, l0, h1, l1;
                splitb(hv.x * ga, h0, l0);
                splitb(hv.y * gb, h1, l1);
                *(__nv_bfloat162*)(hi + q) = __nv_bfloat162(h0, h1);
                *(__nv_bfloat162*)(lo + q) = __nv_bfloat162(l0, l1);
            }
            __threadfence();
            __syncthreads();
            if (tid == 0) atomicAdd(&g_sflag[mt], 1);
            return;
        }
        // ---- out tile ----
        const int oi = r - 8;
        const int b = oi >> 3, nt = oi & 7;
        const int mt = b * 16 + tt;
        if (tid == 0) {
            while (ld_acq(&g_sflag[mt]) < 1) __nanosleep(512);
            while (ld_acq(&g_dxflag[mt]) < 8) __nanosleep(512);
        }
        __syncthreads();

        float acc[4][4][4];
#pragma unroll
        for (int a = 0; a < 4; a++)
#pragma unroll
            for (int bq = 0; bq < 4; bq++)
#pragma unroll
                for (int c = 0; c < 4; c++) acc[a][bq][c] = 0.f;
        hmma_acc<6>(g_hhi + (size_t)mt * 128 * 192, g_hlo + (size_t)mt * 128 * 192,
                    g_wohi + (size_t)nt * 128 * 192, g_wolo + (size_t)nt * 128 * 192,
                    192, dsm, acc);

        const int lane = tid & 31, warp = tid >> 5;
        const int wm = warp >> 2, wn = warp & 3;
        const int g = lane >> 2, tg = lane & 3;
#pragma unroll
        for (int mt4 = 0; mt4 < 4; mt4++) {
            int r0 = wm * 64 + mt4 * 16 + g;
#pragma unroll
            for (int half = 0; half < 2; half++) {
                int row = r0 + half * 8;
                int t = mt * 128 + row;
                float g0 = sigm(g_P1[(size_t)t * P1LD + 448]);
                float g1 = sigm(g_P1[(size_t)t * P1LD + 449]);
                const float* dxrow = g_dx + (size_t)t * DIMD;
                float* orow = out + (size_t)t * DIMD;
#pragma unroll
                for (int nt4 = 0; nt4 < 4; nt4++) {
                    int col = nt * 128 + wn * 32 + nt4 * 8 + tg * 2;
                    float2 dxv = *(const float2*)(dxrow + col);
                    float a0 = acc[mt4][nt4][half * 2 + 0];
                    float a1 = acc[mt4][nt4][half * 2 + 1];
                    float2 o;
                    o.x = a0 + g0 * (Cb[col]     + Db[col]     + dxv.x) + g1 * pb[col];
                    o.y = a1 + g0 * (Cb[col + 1] + Db[col + 1] + dxv.y) + g1 * pb[col + 1];
                    *(float2*)(orow + col) = o;
                }
            }
        }
        return;
    }

    if (blockIdx.x >= BID_DX) {
        // ---- dx tile (tt-major) ----
        const int bt = blockIdx.x - BID_DX;
        const int tt = bt >> 6, rem = bt & 63;
        const int b = rem >> 3, nt = rem & 7;
        const int mt = b * 16 + tt;
        float acc[4][4][4];
#pragma unroll
        for (int a = 0; a < 4; a++)
#pragma unroll
            for (int bq = 0; bq < 4; bq++)
#pragma unroll
                for (int c = 0; c < 4; c++) acc[a][bq][c] = 0.f;
        hmma_acc<32>(g_xhi + (size_t)mt * 128 * DIMD, g_xlo + (size_t)mt * 128 * DIMD,
                     g_whi + (size_t)(512 + nt * 128) * DIMD, g_wlo + (size_t)(512 + nt * 128) * DIMD,
                     DIMD, dsm, acc);
        hmma_store_bias(acc, g_dx + (size_t)mt * 128 * DIMD + nt * 128, DIMD, nullptr);
        __threadfence();
        __syncthreads();
        if (tid == 0) atomicAdd(&g_dxflag[mt], 1);
        return;
    }

    if (blockIdx.x >= 16) {
        // ---- p1 tile (tt-major) ----
        const int idx = blockIdx.x - 16;
        const int tt = idx >> 5, rem = idx & 31;
        const int b = rem >> 2, nt = rem & 3;
        const int mt = b * 16 + tt;
        float acc[4][4][4];
#pragma unroll
        for (int a = 0; a < 4; a++)
#pragma unroll
            for (int bq = 0; bq < 4; bq++)
#pragma unroll
                for (int c = 0; c < 4; c++) acc[a][bq][c] = 0.f;
        hmma_acc<32>(g_xhi + (size_t)mt * 128 * DIMD, g_xlo + (size_t)mt * 128 * DIMD,
                     g_whi + (size_t)nt * 128 * DIMD, g_wlo + (size_t)nt * 128 * DIMD,
                     DIMD, dsm, acc);
        hmma_store_bias(acc, g_P1 + (size_t)mt * 128 * P1LD + nt * 128, P1LD, g_b1 + nt * 128);
        __threadfence();
        __syncthreads();
        if (tid == 0) atomicAdd(&g_p1flag[mt], 1);
        return;
    }

    if (blockIdx.x < 8) {
        // ---- GRU ----
        const int b = blockIdx.x;
        const int j = tid >> 1, k = tid & 1;
        const int jpos = j + ((j >= 64) ? 4 : 0);
        const float* p1 = g_P1 + (size_t)b * SEQ * P1LD;

        ULL wr[32], wz[32], wn[32];
        const float* wb = W_hh + (size_t)j * RNND + k * 64;
#pragma unroll
        for (int i = 0; i < 32; i++) {
            wr[i] = *(const ULL*)(wb + 2 * i);
            wz[i] = *(const ULL*)(wb + 128 * RNND + 2 * i);
            wn[i] = *(const ULL*)(wb + 256 * RNND + 2 * i);
        }
        const float br = b_hh[j], bz = b_hh[RNND + j], bn = b_hh[2 * RNND + j];
        if (tid < 136) { sh[0][tid] = 0.f; sh[1][tid] = 0.f; }

        wait_p1_tile(b * 16);
        const uint32_t rbase = smem_u32(&ring[0][0]);
#pragma unroll
        for (int pre = 0; pre < 7; pre++) {
            if (tid < 96) cpa16(rbase + pre * 1536 + tid * 16, p1 + (size_t)pre * P1LD + 64 + tid * 4);
            CP_COMMIT();
        }
        CP_WAIT(6);
        __syncthreads();

        float* hout = g_HsHr + (size_t)b * SEQ * 192 + 64;
        int buf = 0;

        for (int t = 0; t < SEQ; t++) {
            int tp = t + 7;
            if (tp < SEQ) {
                if ((tp & 127) == 0) wait_p1_tile(b * 16 + (tp >> 7));
                if (tid < 96)
                    cpa16(rbase + (tp & 7) * 1536 + tid * 16, p1 + (size_t)tp * P1LD + 64 + tid * 4);
            }
            CP_COMMIT();

            const float* rg = ring[t & 7];
            float ir = rg[j], iz = rg[128 + j], in0 = rg[256 + j];

            ULL ar = 0ull, az = 0ull, an = 0ull;
            const ulonglong2* h4 = (const ulonglong2*)&sh[buf][k * 68];
#pragma unroll
            for (int i = 0; i < 16; i++) {
                ulonglong2 hv = h4[i];
                fma2(ar, wr[2*i], hv.x); fma2(az, wz[2*i], hv.x); fma2(an, wn[2*i], hv.x);
                fma2(ar, wr[2*i+1], hv.y); fma2(az, wz[2*i+1], hv.y); fma2(an, wn[2*i+1], hv.y);
            }
            float2 fr = upk2(ar), fz = upk2(az), fn = upk2(an);
            float sr = fr.x + fr.y, sz = fz.x + fz.y, sn = fn.x + fn.y;
            sr += __shfl_xor_sync(0xffffffffu, sr, 1);
            sz += __shfl_xor_sync(0xffffffffu, sz, 1);
            sn += __shfl_xor_sync(0xffffffffu, sn, 1);
            float hold = sh[buf][jpos];
            float r = sigm(ir + br + sr);
            float z = sigm(iz + bz + sz);
            float n = tanhf_(in0 + r * (sn + bn));
            float hnew = n + z * (hold - n);
            sh[buf ^ 1][jpos] = hnew;
            if (k == 0) hout[(size_t)t * 192 + j] = hnew;
            buf ^= 1;
            CP_WAIT(6);
            __syncthreads();
            if ((t & 127) == 127) {
                __threadfence();
                __syncthreads();
                if (tid == 0) atomicAdd(&g_scanflagG[b], 1);
            }
        }
    } else {
        // ---- SSM ----
        const int b = blockIdx.x - 8;
        const int j = tid >> 2, k = tid & 3;
        float* shf = (float*)sh;
        const int jpos = (j >> 4) * 20 + (j & 15);
        const float* p1 = g_P1 + (size_t)b * SEQ * P1LD;
        ULL wa[8];
        const float* ab = A + (size_t)j * SSMD + k * 16;
#pragma unroll
        for (int i = 0; i < 8; i++) wa[i] = *(const ULL*)(ab + 2 * i);
        if (tid < 160) shf[tid] = 0.f;

        wait_p1_tile(b * 16);
        const uint32_t rbase = smem_u32(&ring[0][0]);
#pragma unroll
        for (int pre = 0; pre < 7; pre++) {
            if (tid < 16) cpa16(rbase + pre * 1536 + tid * 16, p1 + (size_t)pre * P1LD + tid * 4);
            CP_COMMIT();
        }
        CP_WAIT(6);
        __syncthreads();

        float* hout = g_HsHr + (size_t)b * SEQ * 192;
        int buf = 0;

        for (int t = 0; t < SEQ; t++) {
            int tp = t + 7;
            if (tp < SEQ) {
                if ((tp & 127) == 0) wait_p1_tile(b * 16 + (tp >> 7));
                if (tid < 16)
                    cpa16(rbase + (tp & 7) * 1536 + tid * 16, p1 + (size_t)tp * P1LD + tid * 4);
            }
            CP_COMMIT();

            float bx = ring[t & 7][j];
            ULL acc = 0ull;
            const ULL* hh = (const ULL*)(shf + buf * 80 + k * 20);
#pragma unroll
            for (int i = 0; i < 8; i++) fma2(acc, wa[i], hh[i]);
            float2 fa = upk2(acc);
            float s = fa.x + fa.y;
            s += __shfl_xor_sync(0xffffffffu, s, 1);
            s += __shfl_xor_sync(0xffffffffu, s, 2);
            float pre = s + bx;
            float hnew = pre * sigm(pre);
            shf[(buf ^ 1) * 80 + jpos] = hnew;
            if (k == 0) hout[(size_t)t * 192 + j] = hnew;
            buf ^= 1;
            CP_WAIT(6);
            __syncthreads();
            if ((t & 127) == 127) {
                __threadfence();
                __syncthreads();
                if (tid == 0) atomicAdd(&g_scanflagS[b], 1);
            }
        }
    }
}

extern "C" void kernel_launch(void* const* d_in, const int* in_sizes, int n_in,
                              void* d_out, int out_size) {
    const float* x      = (const float*)d_in[0];
    const float* A      = (const float*)d_in[1];
    const float* Bw     = (const float*)d_in[2];
    const float* Bb     = (const float*)d_in[3];
    const float* Cw     = (const float*)d_in[4];
    const float* Cb     = (const float*)d_in[5];
    const float* Dw     = (const float*)d_in[6];
    const float* Db     = (const float*)d_in[7];
    const float* W_ih   = (const float*)d_in[8];
    const float* b_ih   = (const float*)d_in[9];
    const float* W_hh   = (const float*)d_in[10];
    const float* b_hh   = (const float*)d_in[11];
    const float* proj_w = (const float*)d_in[12];
    const float* proj_b = (const float*)d_in[13];
    const float* gate_w = (const float*)d_in[14];
    const float* gate_b = (const float*)d_in[15];
    float* out = (float*)d_out;

    cudaFuncSetAttribute(mega_kernel, cudaFuncAttributeMaxDynamicSharedMemorySize, DSMB);

    conv_kernel<<<CONVX_BLKS + CONVW_BLKS, 256>>>(x, Bw, Bb, W_ih, b_ih, gate_w, gate_b, Cw, proj_w, Dw);
    mega_kernel<<<N_MEGA, 256, DSMB>>>(A, W_hh, b_hh, Cb, Db, proj_b, out);
}